// round 1
// baseline (speedup 1.0000x reference)
#include <cuda_runtime.h>

#define DDIM 1024
#define DMASK 1023
#define NTHREADS 256
#define EPT 4            // elements per thread (NTHREADS*EPT == DDIM)
#define NWARPS (NTHREADS / 32)
#define HALF_DT 0.05f
#define CG_ITERS 20
#define NOFFS 11

__device__ __forceinline__ float blockReduceSum(float v, float* sred, int tid) {
    #pragma unroll
    for (int o = 16; o > 0; o >>= 1) v += __shfl_xor_sync(0xffffffffu, v, o);
    if ((tid & 31) == 0) sred[tid >> 5] = v;
    __syncthreads();
    if (tid < 32) {
        float s = (tid < NWARPS) ? sred[tid] : 0.0f;
        #pragma unroll
        for (int o = 4; o > 0; o >>= 1) s += __shfl_xor_sync(0xffffffffu, s, o);
        if (tid == 0) sred[0] = s;
    }
    __syncthreads();
    float r = sred[0];
    __syncthreads();   // sred reusable after this
    return r;
}

// H v per component: H = 2W*v - sum_k wm[k]*(v[i+k] + v[i-k]), circular in DDIM
__device__ __forceinline__ float2 ham_stencil(const float2* __restrict__ sp, int i,
                                              float2 center, const float* wm, float twoW) {
    const int offs[NOFFS] = {1, 2, 3, 4, 5, 6, 8, 10, 12, 16, 20};
    float sx = 0.0f, sy = 0.0f;
    #pragma unroll
    for (int k = 0; k < NOFFS; k++) {
        float2 a = sp[(i + offs[k]) & DMASK];
        float2 b = sp[(i - offs[k]) & DMASK];
        sx = fmaf(wm[k], a.x + b.x, sx);
        sy = fmaf(wm[k], a.y + b.y, sy);
    }
    return make_float2(fmaf(twoW, center.x, -sx), fmaf(twoW, center.y, -sy));
}

__global__ __launch_bounds__(NTHREADS)
void cayley_soliton_kernel(const float* __restrict__ psi_r,
                           const float* __restrict__ psi_i,
                           const float* __restrict__ alpha,
                           const float* __restrict__ hw,
                           float2* __restrict__ out) {
    __shared__ float2 sp[DDIM];
    __shared__ float sred[32];

    const int tid = threadIdx.x;
    const long long sys = blockIdx.x;
    const float* __restrict__ gr = psi_r + sys * DDIM;
    const float* __restrict__ gi = psi_i + sys * DDIM;

    // ---- merged stencil weights: offsets {1,2,3,4,5,6,8,10,12,16,20} ----
    float w[15];
    #pragma unroll
    for (int k = 0; k < 15; k++) w[k] = hw[k];
    float wm[NOFFS];
    wm[0]  = w[0];
    wm[1]  = w[1] + w[5];
    wm[2]  = w[2];
    wm[3]  = w[3] + w[6] + w[10];
    wm[4]  = w[4];
    wm[5]  = w[7];
    wm[6]  = w[8] + w[11];
    wm[7]  = w[9];
    wm[8]  = w[12];
    wm[9]  = w[13];
    wm[10] = w[14];
    float Wsum = 0.0f;
    #pragma unroll
    for (int k = 0; k < NOFFS; k++) Wsum += wm[k];
    const float twoW = 2.0f * Wsum;

    // ---- load psi, intensity sum ----
    float2 psi[EPT];
    float isum = 0.0f;
    #pragma unroll
    for (int e = 0; e < EPT; e++) {
        int i = tid + e * NTHREADS;
        psi[e] = make_float2(gr[i], gi[i]);
        isum += psi[e].x * psi[e].x + psi[e].y * psi[e].y;
    }
    float itot = blockReduceSum(isum, sred, tid);
    const float inv_mean = 1.0f / (itot * (1.0f / DDIM) + 1e-8f);

    // ---- nonlinear phase rotation; stage rot into SMEM for stencil ----
    float2 rot[EPT];
    #pragma unroll
    for (int e = 0; e < EPT; e++) {
        int i = tid + e * NTHREADS;
        float inten = (psi[e].x * psi[e].x + psi[e].y * psi[e].y) * inv_mean;
        float ph = alpha[i] * inten;
        float s, c;
        __sincosf(ph, &s, &c);
        rot[e] = make_float2(psi[e].x * c - psi[e].y * s,
                             psi[e].x * s + psi[e].y * c);
        sp[i] = rot[e];
    }
    __syncthreads();

    // ---- rhs b = (I - i*dt/2*H) rot ; init CG state ----
    float2 xx[EPT], rr[EPT], pp[EPT];
    float rs_loc = 0.0f;
    #pragma unroll
    for (int e = 0; e < EPT; e++) {
        int i = tid + e * NTHREADS;
        float2 H = ham_stencil(sp, i, rot[e], wm, twoW);
        float2 b = make_float2(fmaf(HALF_DT, H.y, rot[e].x),
                               fmaf(-HALF_DT, H.x, rot[e].y));
        rr[e] = b;
        pp[e] = b;
        xx[e] = make_float2(0.0f, 0.0f);
        rs_loc += b.x * b.x + b.y * b.y;
    }
    __syncthreads();   // all stencil reads of rot complete
    #pragma unroll
    for (int e = 0; e < EPT; e++) sp[tid + e * NTHREADS] = pp[e];
    float rs = blockReduceSum(rs_loc, sred, tid);  // also fences sp stores
    const float thresh = 1e-12f * fmaxf(rs, 1e-30f);

    // ---- CG loop (early exit == reference's frozen mask, per-system) ----
    for (int it = 0; it < CG_ITERS; it++) {
        if (rs <= thresh) break;

        float2 Ap[EPT];
        float pAp_loc = 0.0f;
        #pragma unroll
        for (int e = 0; e < EPT; e++) {
            int i = tid + e * NTHREADS;
            float2 H = ham_stencil(sp, i, pp[e], wm, twoW);
            Ap[e] = make_float2(fmaf(-HALF_DT, H.y, pp[e].x),
                                fmaf(HALF_DT, H.x, pp[e].y));
            pAp_loc += pp[e].x * Ap[e].x + pp[e].y * Ap[e].y;
        }
        float pAp = blockReduceSum(pAp_loc, sred, tid);
        float a = rs / (pAp + 1e-30f);

        float rs_loc2 = 0.0f;
        #pragma unroll
        for (int e = 0; e < EPT; e++) {
            xx[e].x = fmaf(a, pp[e].x, xx[e].x);
            xx[e].y = fmaf(a, pp[e].y, xx[e].y);
            rr[e].x = fmaf(-a, Ap[e].x, rr[e].x);
            rr[e].y = fmaf(-a, Ap[e].y, rr[e].y);
            rs_loc2 += rr[e].x * rr[e].x + rr[e].y * rr[e].y;
        }
        float rs_new = blockReduceSum(rs_loc2, sred, tid);
        float beta = rs_new / (rs + 1e-30f);

        #pragma unroll
        for (int e = 0; e < EPT; e++) {
            pp[e].x = fmaf(beta, pp[e].x, rr[e].x);
            pp[e].y = fmaf(beta, pp[e].y, rr[e].y);
            sp[tid + e * NTHREADS] = pp[e];   // safe: reductions fenced old reads
        }
        rs = rs_new;
        __syncthreads();
    }

    // ---- write x ----
    float2* __restrict__ o = out + sys * DDIM;
    #pragma unroll
    for (int e = 0; e < EPT; e++) o[tid + e * NTHREADS] = xx[e];
}

extern "C" void kernel_launch(void* const* d_in, const int* in_sizes, int n_in,
                              void* d_out, int out_size) {
    const float* psi_r = (const float*)d_in[0];
    const float* psi_i = (const float*)d_in[1];
    const float* alpha = (const float*)d_in[2];
    const float* ham_w = (const float*)d_in[3];
    float2* out = (float2*)d_out;

    const int nsys = in_sizes[0] / DDIM;   // B*S = 16384
    cayley_soliton_kernel<<<nsys, NTHREADS>>>(psi_r, psi_i, alpha, ham_w, out);
}

// round 2
// speedup vs baseline: 11.1832x; 11.1832x over previous
#include <cuda_runtime.h>

#define NTH 256
#define HALF_DT 0.05f

__device__ float2 g_mult[1024];   // conj(M[rev4(p)]) / 1024, digit-reversed order

__device__ __forceinline__ float2 cadd(float2 a, float2 b){ return make_float2(a.x+b.x, a.y+b.y); }
__device__ __forceinline__ float2 csub(float2 a, float2 b){ return make_float2(a.x-b.x, a.y-b.y); }
__device__ __forceinline__ float2 cmul(float2 a, float2 b){
    return make_float2(fmaf(a.x, b.x, -a.y*b.y), fmaf(a.x, b.y, a.y*b.x));
}

// ---------- pre-kernel: spectral Cayley multiplier, digit-reversed + conj + 1/N ----------
__global__ void build_mult(const float* __restrict__ hw) {
    int p = blockIdx.x * blockDim.x + threadIdx.x;   // 0..1023
    if (p >= 1024) return;
    float w[15];
    #pragma unroll
    for (int k = 0; k < 15; k++) w[k] = hw[k];
    const int offs[11] = {1,2,3,4,5,6,8,10,12,16,20};
    float wm[11];
    wm[0]=w[0]; wm[1]=w[1]+w[5]; wm[2]=w[2]; wm[3]=w[3]+w[6]+w[10]; wm[4]=w[4];
    wm[5]=w[7]; wm[6]=w[8]+w[11]; wm[7]=w[9]; wm[8]=w[12]; wm[9]=w[13]; wm[10]=w[14];
    // base-4 digit reversal of p (5 digits) -> frequency f stored at position p
    int f = ((p & 3) << 8) | (((p >> 2) & 3) << 6) | (((p >> 4) & 3) << 4)
          | (((p >> 6) & 3) << 2) | ((p >> 8) & 3);
    float lam = 0.0f;
    #pragma unroll
    for (int k = 0; k < 11; k++)
        lam += 2.0f * wm[k] * (1.0f - cospif((float)(offs[k] * f) * (1.0f/512.0f)));
    float sl  = HALF_DT * lam;
    float den = 1.0f + sl * sl;
    // M(f) = ((1 - sl^2) - 2 i sl)/den ;  store conj(M)/1024
    g_mult[p] = make_float2((1.0f - sl*sl) / (den * 1024.0f),
                            (2.0f * sl)    / (den * 1024.0f));
}

// ---------- butterflies ----------
// DIF: combine then twiddle (forward, W = e^{-2pi i /L})
__device__ __forceinline__ void dif4(float2 v[4], float2 W1) {
    float2 t0 = cadd(v[0], v[2]), t1 = csub(v[0], v[2]);
    float2 t2 = cadd(v[1], v[3]), t3 = csub(v[1], v[3]);
    float2 u0 = cadd(t0, t2);
    float2 u1 = make_float2(t1.x + t3.y, t1.y - t3.x);   // t1 - i t3
    float2 u2 = csub(t0, t2);
    float2 u3 = make_float2(t1.x - t3.y, t1.y + t3.x);   // t1 + i t3
    float2 W2 = cmul(W1, W1), W3 = cmul(W1, W2);
    v[0] = u0; v[1] = cmul(u1, W1); v[2] = cmul(u2, W2); v[3] = cmul(u3, W3);
}
// combine-only (twiddle == 1): shared by DIF last stage and DIT first stage
__device__ __forceinline__ void bfly4_nt(float2 v[4]) {
    float2 t0 = cadd(v[0], v[2]), t1 = csub(v[0], v[2]);
    float2 t2 = cadd(v[1], v[3]), t3 = csub(v[1], v[3]);
    v[0] = cadd(t0, t2);
    v[1] = make_float2(t1.x + t3.y, t1.y - t3.x);
    v[2] = csub(t0, t2);
    v[3] = make_float2(t1.x - t3.y, t1.y + t3.x);
}
// DIT: twiddle inputs then combine
__device__ __forceinline__ void dit4(float2 v[4], float2 W1) {
    float2 W2 = cmul(W1, W1), W3 = cmul(W1, W2);
    float2 b = cmul(v[1], W1), c = cmul(v[2], W2), d = cmul(v[3], W3);
    float2 t0 = cadd(v[0], c), t1 = csub(v[0], c);
    float2 t2 = cadd(b, d),    t3 = csub(b, d);
    v[0] = cadd(t0, t2);
    v[1] = make_float2(t1.x + t3.y, t1.y - t3.x);
    v[2] = csub(t0, t2);
    v[3] = make_float2(t1.x - t3.y, t1.y + t3.x);
}

// stage ownership index maps
#define I1(t,k) ((t) + ((k) << 8))
#define I2(t,k) (((((t) >> 6)) << 8) + ((t) & 63) + ((k) << 6))
#define I3(t,k) (((((t) >> 4)) << 6) + ((t) & 15) + ((k) << 4))
#define I4(t,k) (((((t) >> 2)) << 4) + ((t) & 3)  + ((k) << 2))
#define I5(t,k) (((t) << 2) + (k))
__device__ __forceinline__ int sw(int i) { return i ^ ((i >> 2) & 15); }

__device__ __forceinline__ float blockReduceSum(float v, float* sred, int tid) {
    #pragma unroll
    for (int o = 16; o > 0; o >>= 1) v += __shfl_xor_sync(0xffffffffu, v, o);
    if ((tid & 31) == 0) sred[tid >> 5] = v;
    __syncthreads();
    if (tid < 32) {
        float s = (tid < 8) ? sred[tid] : 0.0f;
        #pragma unroll
        for (int o = 4; o > 0; o >>= 1) s += __shfl_xor_sync(0xffffffffu, s, o);
        if (tid == 0) sred[0] = s;
    }
    __syncthreads();
    float r = sred[0];
    __syncthreads();
    return r;
}

__global__ __launch_bounds__(NTH)
void cayley_fft_kernel(const float* __restrict__ psi_r,
                       const float* __restrict__ psi_i,
                       const float* __restrict__ alpha,
                       float2* __restrict__ out) {
    __shared__ float2 sx[1024];
    __shared__ float2 tw1[256];
    __shared__ float2 tw2[64];
    __shared__ float2 tw3[16];
    __shared__ float2 tw4[4];
    __shared__ float  sred[32];

    const int t = threadIdx.x;
    const long long sys = blockIdx.x;
    const float* __restrict__ gr = psi_r + sys * 1024;
    const float* __restrict__ gi = psi_i + sys * 1024;

    // twiddle tables: W_L^j laid out per stage so warp reads are consecutive/broadcast
    {
        float s, c;
        sincospif((float)t * (1.0f/512.0f), &s, &c);  tw1[t] = make_float2(c, -s);
        if (t < 64) { sincospif((float)t * (1.0f/128.0f), &s, &c); tw2[t] = make_float2(c, -s); }
        if (t < 16) { sincospif((float)t * (1.0f/32.0f),  &s, &c); tw3[t] = make_float2(c, -s); }
        if (t < 4)  { sincospif((float)t * (1.0f/8.0f),   &s, &c); tw4[t] = make_float2(c, -s); }
    }

    // ---- load psi (already in S1 layout: stride-256), intensity ----
    float2 v[4];
    float isum = 0.0f;
    #pragma unroll
    for (int k = 0; k < 4; k++) {
        int i = I1(t, k);
        v[k] = make_float2(gr[i], gi[i]);
        isum += v[k].x * v[k].x + v[k].y * v[k].y;
    }
    float itot = blockReduceSum(isum, sred, t);   // syncs also publish tw tables
    const float inv_mean = 1.0f / (itot * (1.0f/1024.0f) + 1e-8f);

    // ---- nonlinear phase rotation (in regs) ----
    #pragma unroll
    for (int k = 0; k < 4; k++) {
        int i = I1(t, k);
        float inten = (v[k].x * v[k].x + v[k].y * v[k].y) * inv_mean;
        float ph = alpha[i] * inten;
        float s, c;
        __sincosf(ph, &s, &c);
        v[k] = make_float2(v[k].x * c - v[k].y * s, v[k].x * s + v[k].y * c);
    }

    // ================= forward FFT: DIF stages =================
    dif4(v, tw1[t]);                                     // S1 (span 1024, j=t)
    #pragma unroll
    for (int k = 0; k < 4; k++) sx[I1(t, k)] = v[k];
    __syncthreads();
    #pragma unroll
    for (int k = 0; k < 4; k++) v[k] = sx[I2(t, k)];
    __syncthreads();

    dif4(v, tw2[t & 63]);                                // S2 (span 256)
    #pragma unroll
    for (int k = 0; k < 4; k++) sx[I2(t, k)] = v[k];
    __syncthreads();
    #pragma unroll
    for (int k = 0; k < 4; k++) v[k] = sx[I3(t, k)];
    __syncthreads();

    dif4(v, tw3[t & 15]);                                // S3 (span 64)
    #pragma unroll
    for (int k = 0; k < 4; k++) sx[sw(I3(t, k))] = v[k];
    __syncthreads();
    #pragma unroll
    for (int k = 0; k < 4; k++) v[k] = sx[sw(I4(t, k))];
    __syncthreads();

    dif4(v, tw4[t & 3]);                                 // S4 (span 16)
    #pragma unroll
    for (int k = 0; k < 4; k++) sx[sw(I4(t, k))] = v[k];
    __syncthreads();
    #pragma unroll
    for (int k = 0; k < 4; k++) v[k] = sx[sw(I5(t, k))];
    __syncthreads();

    bfly4_nt(v);                                         // S5 (span 4, twiddle-free)

    // ===== spectral multiply (digit-reversed order), conj trick folded in =====
    {
        const float4* Mp = (const float4*)g_mult;
        float4 m01 = Mp[2 * t], m23 = Mp[2 * t + 1];
        float2 T[4] = { make_float2(m01.x, m01.y), make_float2(m01.z, m01.w),
                        make_float2(m23.x, m23.y), make_float2(m23.z, m23.w) };
        #pragma unroll
        for (int k = 0; k < 4; k++) {
            float2 F = make_float2(v[k].x, -v[k].y);     // conj
            v[k] = cmul(F, T[k]);
        }
    }

    // ================= inverse (conj-trick forward DIT) =================
    bfly4_nt(v);                                         // D1 (span 4, twiddle-free)
    #pragma unroll
    for (int k = 0; k < 4; k++) sx[sw(I5(t, k))] = v[k];
    __syncthreads();
    #pragma unroll
    for (int k = 0; k < 4; k++) v[k] = sx[sw(I4(t, k))];
    __syncthreads();

    dit4(v, tw4[t & 3]);                                 // D2 (span 16)
    #pragma unroll
    for (int k = 0; k < 4; k++) sx[sw(I4(t, k))] = v[k];
    __syncthreads();
    #pragma unroll
    for (int k = 0; k < 4; k++) v[k] = sx[sw(I3(t, k))];
    __syncthreads();

    dit4(v, tw3[t & 15]);                                // D3 (span 64)
    #pragma unroll
    for (int k = 0; k < 4; k++) sx[I3(t, k)] = v[k];
    __syncthreads();
    #pragma unroll
    for (int k = 0; k < 4; k++) v[k] = sx[I2(t, k)];
    __syncthreads();

    dit4(v, tw2[t & 63]);                                // D4 (span 256)
    #pragma unroll
    for (int k = 0; k < 4; k++) sx[I2(t, k)] = v[k];
    __syncthreads();
    #pragma unroll
    for (int k = 0; k < 4; k++) v[k] = sx[I1(t, k)];
    __syncthreads();

    dit4(v, tw1[t]);                                     // D5 (span 1024)

    // ---- final conj + store (coalesced) ----
    float2* __restrict__ o = out + sys * 1024;
    #pragma unroll
    for (int k = 0; k < 4; k++) {
        int i = I1(t, k);
        o[i] = make_float2(v[k].x, -v[k].y);
    }
}

extern "C" void kernel_launch(void* const* d_in, const int* in_sizes, int n_in,
                              void* d_out, int out_size) {
    const float* psi_r = (const float*)d_in[0];
    const float* psi_i = (const float*)d_in[1];
    const float* alpha = (const float*)d_in[2];
    const float* ham_w = (const float*)d_in[3];
    float2* out = (float2*)d_out;

    const int nsys = in_sizes[0] / 1024;   // B*S = 16384

    build_mult<<<4, 256>>>(ham_w);
    cayley_fft_kernel<<<nsys, NTH>>>(psi_r, psi_i, alpha, out);
}

// round 3
// speedup vs baseline: 18.0556x; 1.6145x over previous
#include <cuda_runtime.h>

#define HALF_DT 0.05f

__device__ float2 g_mult[1024];   // conj(M[rev4(p)]) / 1024, digit-reversed order

__device__ __forceinline__ float2 cadd(float2 a, float2 b){ return make_float2(a.x+b.x, a.y+b.y); }
__device__ __forceinline__ float2 csub(float2 a, float2 b){ return make_float2(a.x-b.x, a.y-b.y); }
__device__ __forceinline__ float2 cmul(float2 a, float2 b){
    return make_float2(fmaf(a.x, b.x, -a.y*b.y), fmaf(a.x, b.y, a.y*b.x));
}

// ---------- pre-kernel: spectral Cayley multiplier, digit-reversed + conj + 1/N ----------
__global__ void build_mult(const float* __restrict__ hw) {
    int p = blockIdx.x * blockDim.x + threadIdx.x;   // 0..1023
    if (p >= 1024) return;
    float w[15];
    #pragma unroll
    for (int k = 0; k < 15; k++) w[k] = hw[k];
    const int offs[11] = {1,2,3,4,5,6,8,10,12,16,20};
    float wm[11];
    wm[0]=w[0]; wm[1]=w[1]+w[5]; wm[2]=w[2]; wm[3]=w[3]+w[6]+w[10]; wm[4]=w[4];
    wm[5]=w[7]; wm[6]=w[8]+w[11]; wm[7]=w[9]; wm[8]=w[12]; wm[9]=w[13]; wm[10]=w[14];
    int f = ((p & 3) << 8) | (((p >> 2) & 3) << 6) | (((p >> 4) & 3) << 4)
          | (((p >> 6) & 3) << 2) | ((p >> 8) & 3);
    float lam = 0.0f;
    #pragma unroll
    for (int k = 0; k < 11; k++)
        lam += 2.0f * wm[k] * (1.0f - cospif((float)(offs[k] * f) * (1.0f/512.0f)));
    float sl  = HALF_DT * lam;
    float den = 1.0f + sl * sl;
    g_mult[p] = make_float2((1.0f - sl*sl) / (den * 1024.0f),
                            (2.0f * sl)    / (den * 1024.0f));
}

// ---------- butterflies (reference-parameter form) ----------
__device__ __forceinline__ void bfly4p(float2& A, float2& B, float2& C, float2& D) {
    float2 t0 = cadd(A, C), t1 = csub(A, C);
    float2 t2 = cadd(B, D), t3 = csub(B, D);
    A = cadd(t0, t2);
    B = make_float2(t1.x + t3.y, t1.y - t3.x);   // t1 - i t3
    C = csub(t0, t2);
    D = make_float2(t1.x - t3.y, t1.y + t3.x);   // t1 + i t3
}
// DIF: combine then twiddle (W = e^{-2pi i m/L})
__device__ __forceinline__ void dif4p(float2& A, float2& B, float2& C, float2& D, float2 W1) {
    bfly4p(A, B, C, D);
    float2 W2 = cmul(W1, W1), W3 = cmul(W1, W2);
    B = cmul(B, W1); C = cmul(C, W2); D = cmul(D, W3);
}
// DIT: twiddle inputs then combine
__device__ __forceinline__ void dit4p(float2& A, float2& B, float2& C, float2& D, float2 W1) {
    float2 W2 = cmul(W1, W1), W3 = cmul(W1, W2);
    B = cmul(B, W1); C = cmul(C, W2); D = cmul(D, W3);
    bfly4p(A, B, C, D);
}

// layouts (t = 0..63)
#define N1(t,k) ((t) + ((k) << 6))
#define N2(t,j) ((((t) >> 2) << 6) + ((t) & 3) + (((j) & 3) << 2) + (((j) >> 2) << 4))
#define N3(t,e) (((t) << 4) + (e))
// bank swizzles (conflict-free on both sides of each exchange)
__device__ __forceinline__ int swA(int n) { return n ^ (((n >> 6) & 3) << 2); }
__device__ __forceinline__ int swB(int n) { return n ^ ((n >> 4) & 15); }

__global__ __launch_bounds__(64)
void cayley_fft_kernel(const float* __restrict__ psi_r,
                       const float* __restrict__ psi_i,
                       const float* __restrict__ alpha,
                       float2* __restrict__ out) {
    __shared__ float2 sx[1024];
    __shared__ float  sred[2];

    const int t = threadIdx.x;
    const long long sys = blockIdx.x;
    const float* __restrict__ gr = psi_r + sys * 1024;
    const float* __restrict__ gi = psi_i + sys * 1024;

    // ---- register twiddles ----
    float2 TA[4], TC[4], TB, TW16;
    {
        float s, c;
        #pragma unroll
        for (int q = 0; q < 4; q++) {
            sincospif((float)(t + 64*q) * (1.0f/512.0f), &s, &c); TA[q] = make_float2(c, -s);
        }
        sincospif((float)t * (1.0f/128.0f), &s, &c); TB = make_float2(c, -s);
        #pragma unroll
        for (int a = 0; a < 4; a++) {
            sincospif((float)((t & 3) + 4*a) * (1.0f/32.0f), &s, &c); TC[a] = make_float2(c, -s);
        }
        sincospif((float)(t & 3) * 0.125f, &s, &c); TW16 = make_float2(c, -s);
    }

    // ---- load (L1 layout), intensity ----
    float2 v[16];
    float isum = 0.0f;
    #pragma unroll
    for (int k = 0; k < 16; k++) {
        int i = N1(t, k);
        v[k] = make_float2(gr[i], gi[i]);
        isum += v[k].x * v[k].x + v[k].y * v[k].y;
    }
    #pragma unroll
    for (int o = 16; o > 0; o >>= 1) isum += __shfl_xor_sync(0xffffffffu, isum, o);
    if ((t & 31) == 0) sred[t >> 5] = isum;
    __syncthreads();
    const float itot = sred[0] + sred[1];
    const float inv_mean = 1.0f / (itot * (1.0f/1024.0f) + 1e-8f);

    // ---- nonlinear phase rotation ----
    #pragma unroll
    for (int k = 0; k < 16; k++) {
        int i = N1(t, k);
        float inten = (v[k].x * v[k].x + v[k].y * v[k].y) * inv_mean;
        float ph = alpha[i] * inten;
        float s, c;
        __sincosf(ph, &s, &c);
        v[k] = make_float2(v[k].x * c - v[k].y * s, v[k].x * s + v[k].y * c);
    }

    // ======== forward DIF ========
    #pragma unroll
    for (int q = 0; q < 4; q++)            // S1 span 1024 (stride 256)
        dif4p(v[q], v[q+4], v[q+8], v[q+12], TA[q]);
    #pragma unroll
    for (int B = 0; B < 4; B++)            // S2 span 256 (stride 64)
        dif4p(v[4*B], v[4*B+1], v[4*B+2], v[4*B+3], TB);

    __syncthreads();                        // exchange A: L1 -> L2
    #pragma unroll
    for (int k = 0; k < 16; k++) sx[swA(N1(t, k))] = v[k];
    __syncthreads();
    #pragma unroll
    for (int j = 0; j < 16; j++) v[j] = sx[swA(N2(t, j))];

    #pragma unroll
    for (int a = 0; a < 4; a++)            // S3 span 64 (stride 16)
        dif4p(v[a], v[a+4], v[a+8], v[a+12], TC[a]);
    #pragma unroll
    for (int b = 0; b < 4; b++)            // S4 span 16 (stride 4)
        dif4p(v[4*b], v[4*b+1], v[4*b+2], v[4*b+3], TW16);

    __syncthreads();                        // exchange B: L2 -> L3
    #pragma unroll
    for (int j = 0; j < 16; j++) sx[swB(N2(t, j))] = v[j];
    __syncthreads();
    #pragma unroll
    for (int e = 0; e < 16; e++) v[e] = sx[swB(N3(t, e))];

    #pragma unroll
    for (int c4 = 0; c4 < 4; c4++)         // S5 span 4 (twiddle-free)
        bfly4p(v[4*c4], v[4*c4+1], v[4*c4+2], v[4*c4+3]);

    // ===== spectral multiply (position-indexed, digit-reversed table, conj folded) =====
    {
        const float4* Mp = (const float4*)g_mult;
        #pragma unroll
        for (int c2 = 0; c2 < 8; c2++) {
            float4 m = Mp[8 * t + c2];
            float2 F0 = make_float2(v[2*c2].x,   -v[2*c2].y);
            float2 F1 = make_float2(v[2*c2+1].x, -v[2*c2+1].y);
            v[2*c2]   = cmul(F0, make_float2(m.x, m.y));
            v[2*c2+1] = cmul(F1, make_float2(m.z, m.w));
        }
    }

    // ======== inverse (conj-trick forward DIT) ========
    #pragma unroll
    for (int c4 = 0; c4 < 4; c4++)         // D1 span 4 (twiddle-free)
        bfly4p(v[4*c4], v[4*c4+1], v[4*c4+2], v[4*c4+3]);
    {                                       // D2 span 16 (stride 4), const twiddles
        bfly4p(v[0], v[4], v[8], v[12]);
        dit4p(v[1], v[5], v[9],  v[13], make_float2(0.92387953251f, -0.38268343236f));
        dit4p(v[2], v[6], v[10], v[14], make_float2(0.70710678119f, -0.70710678119f));
        dit4p(v[3], v[7], v[11], v[15], make_float2(0.38268343236f, -0.92387953251f));
    }

    __syncthreads();                        // exchange C: L3 -> L2
    #pragma unroll
    for (int e = 0; e < 16; e++) sx[swB(N3(t, e))] = v[e];
    __syncthreads();
    #pragma unroll
    for (int j = 0; j < 16; j++) v[j] = sx[swB(N2(t, j))];

    #pragma unroll
    for (int a = 0; a < 4; a++)            // D3 span 64 (stride 16)
        dit4p(v[a], v[a+4], v[a+8], v[a+12], TC[a]);

    __syncthreads();                        // exchange D: L2 -> L1
    #pragma unroll
    for (int j = 0; j < 16; j++) sx[swA(N2(t, j))] = v[j];
    __syncthreads();
    #pragma unroll
    for (int k = 0; k < 16; k++) v[k] = sx[swA(N1(t, k))];

    #pragma unroll
    for (int B = 0; B < 4; B++)            // D4 span 256 (stride 64)
        dit4p(v[4*B], v[4*B+1], v[4*B+2], v[4*B+3], TB);
    #pragma unroll
    for (int q = 0; q < 4; q++)            // D5 span 1024 (stride 256)
        dit4p(v[q], v[q+4], v[q+8], v[q+12], TA[q]);

    // ---- final conj + coalesced store ----
    float2* __restrict__ o = out + sys * 1024;
    #pragma unroll
    for (int k = 0; k < 16; k++) {
        int i = N1(t, k);
        o[i] = make_float2(v[k].x, -v[k].y);
    }
}

extern "C" void kernel_launch(void* const* d_in, const int* in_sizes, int n_in,
                              void* d_out, int out_size) {
    const float* psi_r = (const float*)d_in[0];
    const float* psi_i = (const float*)d_in[1];
    const float* alpha = (const float*)d_in[2];
    const float* ham_w = (const float*)d_in[3];
    float2* out = (float2*)d_out;

    const int nsys = in_sizes[0] / 1024;   // B*S = 16384

    build_mult<<<4, 256>>>(ham_w);
    cayley_fft_kernel<<<nsys, 64>>>(psi_r, psi_i, alpha, out);
}

// round 4
// speedup vs baseline: 21.3274x; 1.1812x over previous
#include <cuda_runtime.h>

#define HALF_DT 0.05f

__device__ float2 g_mult[1024];   // conj(M[rev4(p)]) / 1024, digit-reversed order

__device__ __forceinline__ float2 cadd(float2 a, float2 b){ return make_float2(a.x+b.x, a.y+b.y); }
__device__ __forceinline__ float2 csub(float2 a, float2 b){ return make_float2(a.x-b.x, a.y-b.y); }
__device__ __forceinline__ float2 cmul(float2 a, float2 b){
    return make_float2(fmaf(a.x, b.x, -a.y*b.y), fmaf(a.x, b.y, a.y*b.x));
}

// twiddle e^{-i*ang}, ang in [0, pi/2): fast MUFU path, ~2^-21 abs error
__device__ __forceinline__ float2 twd(float ang) {
    float s, c;
    __sincosf(ang, &s, &c);
    return make_float2(c, -s);
}

// ---------- pre-kernel: spectral Cayley multiplier, digit-reversed + conj + 1/N ----------
__global__ void build_mult(const float* __restrict__ hw) {
    int p = blockIdx.x * blockDim.x + threadIdx.x;   // 0..1023
    if (p >= 1024) return;
    float w[15];
    #pragma unroll
    for (int k = 0; k < 15; k++) w[k] = hw[k];
    const int offs[11] = {1,2,3,4,5,6,8,10,12,16,20};
    float wm[11];
    wm[0]=w[0]; wm[1]=w[1]+w[5]; wm[2]=w[2]; wm[3]=w[3]+w[6]+w[10]; wm[4]=w[4];
    wm[5]=w[7]; wm[6]=w[8]+w[11]; wm[7]=w[9]; wm[8]=w[12]; wm[9]=w[13]; wm[10]=w[14];
    int f = ((p & 3) << 8) | (((p >> 2) & 3) << 6) | (((p >> 4) & 3) << 4)
          | (((p >> 6) & 3) << 2) | ((p >> 8) & 3);
    float lam = 0.0f;
    #pragma unroll
    for (int k = 0; k < 11; k++)
        lam += 2.0f * wm[k] * (1.0f - cospif((float)(offs[k] * f) * (1.0f/512.0f)));
    float sl  = HALF_DT * lam;
    float den = 1.0f + sl * sl;
    g_mult[p] = make_float2((1.0f - sl*sl) / (den * 1024.0f),
                            (2.0f * sl)    / (den * 1024.0f));
}

// ---------- butterflies ----------
__device__ __forceinline__ void bfly4p(float2& A, float2& B, float2& C, float2& D) {
    float2 t0 = cadd(A, C), t1 = csub(A, C);
    float2 t2 = cadd(B, D), t3 = csub(B, D);
    A = cadd(t0, t2);
    B = make_float2(t1.x + t3.y, t1.y - t3.x);   // t1 - i t3
    C = csub(t0, t2);
    D = make_float2(t1.x - t3.y, t1.y + t3.x);   // t1 + i t3
}
__device__ __forceinline__ void dif4p(float2& A, float2& B, float2& C, float2& D, float2 W1) {
    bfly4p(A, B, C, D);
    float2 W2 = cmul(W1, W1), W3 = cmul(W1, W2);
    B = cmul(B, W1); C = cmul(C, W2); D = cmul(D, W3);
}
__device__ __forceinline__ void dit4p(float2& A, float2& B, float2& C, float2& D, float2 W1) {
    float2 W2 = cmul(W1, W1), W3 = cmul(W1, W2);
    B = cmul(B, W1); C = cmul(C, W2); D = cmul(D, W3);
    bfly4p(A, B, C, D);
}

// layouts (t = 0..63)
#define N1(t,k) ((t) + ((k) << 6))
#define N2(t,j) ((((t) >> 2) << 6) + ((t) & 3) + (((j) & 3) << 2) + (((j) >> 2) << 4))
#define N3(t,e) (((t) << 4) + (e))
// bank swizzles (conflict-free on both sides of each exchange)
__device__ __forceinline__ int swA(int n) { return n ^ (((n >> 6) & 3) << 2); }
__device__ __forceinline__ int swB(int n) { return n ^ ((n >> 4) & 15); }

#define A1024 0.00613592315f   /* 2*pi/1024 */
#define A256  0.02454369260f   /* 2*pi/256  */
#define A64   0.09817477042f   /* 2*pi/64   */
#define A16   0.39269908170f   /* 2*pi/16   */

__global__ __launch_bounds__(64, 8)
void cayley_fft_kernel(const float* __restrict__ psi_r,
                       const float* __restrict__ psi_i,
                       const float* __restrict__ alpha,
                       float2* __restrict__ out) {
    __shared__ float2 sx[1024];
    __shared__ float  sred[2];

    const int t = threadIdx.x;
    const long long sys = blockIdx.x;
    const float* __restrict__ gr = psi_r + sys * 1024;
    const float* __restrict__ gi = psi_i + sys * 1024;
    const int t3 = t & 3;

    // ---- load (L1 layout), intensity ----
    float2 v[16];
    float isum = 0.0f;
    #pragma unroll
    for (int k = 0; k < 16; k++) {
        int i = N1(t, k);
        v[k] = make_float2(gr[i], gi[i]);
        isum += v[k].x * v[k].x + v[k].y * v[k].y;
    }
    #pragma unroll
    for (int o = 16; o > 0; o >>= 1) isum += __shfl_xor_sync(0xffffffffu, isum, o);
    if ((t & 31) == 0) sred[t >> 5] = isum;
    __syncthreads();
    const float itot = sred[0] + sred[1];
    const float inv_mean = 1.0f / (itot * (1.0f/1024.0f) + 1e-8f);

    // ---- nonlinear phase rotation ----
    #pragma unroll
    for (int k = 0; k < 16; k++) {
        int i = N1(t, k);
        float inten = (v[k].x * v[k].x + v[k].y * v[k].y) * inv_mean;
        float ph = alpha[i] * inten;
        float s, c;
        __sincosf(ph, &s, &c);
        v[k] = make_float2(v[k].x * c - v[k].y * s, v[k].x * s + v[k].y * c);
    }

    // ======== forward DIF ========
    #pragma unroll
    for (int q = 0; q < 4; q++)            // S1 span 1024 (stride 256)
        dif4p(v[q], v[q+4], v[q+8], v[q+12], twd((float)(t + 64*q) * A1024));
    {
        float2 TB = twd((float)t * A256);
        #pragma unroll
        for (int B = 0; B < 4; B++)        // S2 span 256 (stride 64)
            dif4p(v[4*B], v[4*B+1], v[4*B+2], v[4*B+3], TB);
    }

    __syncthreads();                        // exchange A: L1 -> L2
    #pragma unroll
    for (int k = 0; k < 16; k++) sx[swA(N1(t, k))] = v[k];
    __syncthreads();
    #pragma unroll
    for (int j = 0; j < 16; j++) v[j] = sx[swA(N2(t, j))];

    #pragma unroll
    for (int a = 0; a < 4; a++)            // S3 span 64 (stride 16)
        dif4p(v[a], v[a+4], v[a+8], v[a+12], twd((float)(t3 + 4*a) * A64));
    {
        float2 TW16 = twd((float)t3 * A16);
        #pragma unroll
        for (int b = 0; b < 4; b++)        // S4 span 16 (stride 4)
            dif4p(v[4*b], v[4*b+1], v[4*b+2], v[4*b+3], TW16);
    }

    __syncthreads();                        // exchange B: L2 -> L3
    #pragma unroll
    for (int j = 0; j < 16; j++) sx[swB(N2(t, j))] = v[j];
    __syncthreads();
    #pragma unroll
    for (int e = 0; e < 16; e++) v[e] = sx[swB(N3(t, e))];

    #pragma unroll
    for (int c4 = 0; c4 < 4; c4++)         // S5 span 4 (twiddle-free)
        bfly4p(v[4*c4], v[4*c4+1], v[4*c4+2], v[4*c4+3]);

    // ===== spectral multiply (position-indexed, digit-reversed table, conj folded) =====
    {
        const float4* Mp = (const float4*)g_mult;
        #pragma unroll
        for (int c2 = 0; c2 < 8; c2++) {
            float4 m = Mp[8 * t + c2];
            float2 F0 = make_float2(v[2*c2].x,   -v[2*c2].y);
            float2 F1 = make_float2(v[2*c2+1].x, -v[2*c2+1].y);
            v[2*c2]   = cmul(F0, make_float2(m.x, m.y));
            v[2*c2+1] = cmul(F1, make_float2(m.z, m.w));
        }
    }

    // ======== inverse (conj-trick forward DIT) ========
    #pragma unroll
    for (int c4 = 0; c4 < 4; c4++)         // D1 span 4 (twiddle-free)
        bfly4p(v[4*c4], v[4*c4+1], v[4*c4+2], v[4*c4+3]);
    {                                       // D2 span 16 (stride 4), const twiddles
        bfly4p(v[0], v[4], v[8], v[12]);
        dit4p(v[1], v[5], v[9],  v[13], make_float2(0.92387953251f, -0.38268343236f));
        dit4p(v[2], v[6], v[10], v[14], make_float2(0.70710678119f, -0.70710678119f));
        dit4p(v[3], v[7], v[11], v[15], make_float2(0.38268343236f, -0.92387953251f));
    }

    __syncthreads();                        // exchange C: L3 -> L2
    #pragma unroll
    for (int e = 0; e < 16; e++) sx[swB(N3(t, e))] = v[e];
    __syncthreads();
    #pragma unroll
    for (int j = 0; j < 16; j++) v[j] = sx[swB(N2(t, j))];

    #pragma unroll
    for (int a = 0; a < 4; a++)            // D3 span 64 (stride 16)
        dit4p(v[a], v[a+4], v[a+8], v[a+12], twd((float)(t3 + 4*a) * A64));

    __syncthreads();                        // exchange D: L2 -> L1
    #pragma unroll
    for (int j = 0; j < 16; j++) sx[swA(N2(t, j))] = v[j];
    __syncthreads();
    #pragma unroll
    for (int k = 0; k < 16; k++) v[k] = sx[swA(N1(t, k))];

    {
        float2 TB = twd((float)t * A256);
        #pragma unroll
        for (int B = 0; B < 4; B++)        // D4 span 256 (stride 64)
            dit4p(v[4*B], v[4*B+1], v[4*B+2], v[4*B+3], TB);
    }
    #pragma unroll
    for (int q = 0; q < 4; q++)            // D5 span 1024 (stride 256)
        dit4p(v[q], v[q+4], v[q+8], v[q+12], twd((float)(t + 64*q) * A1024));

    // ---- final conj + coalesced store ----
    float2* __restrict__ o = out + sys * 1024;
    #pragma unroll
    for (int k = 0; k < 16; k++) {
        int i = N1(t, k);
        o[i] = make_float2(v[k].x, -v[k].y);
    }
}

extern "C" void kernel_launch(void* const* d_in, const int* in_sizes, int n_in,
                              void* d_out, int out_size) {
    const float* psi_r = (const float*)d_in[0];
    const float* psi_i = (const float*)d_in[1];
    const float* alpha = (const float*)d_in[2];
    const float* ham_w = (const float*)d_in[3];
    float2* out = (float2*)d_out;

    const int nsys = in_sizes[0] / 1024;   // B*S = 16384

    build_mult<<<4, 256>>>(ham_w);
    cayley_fft_kernel<<<nsys, 64>>>(psi_r, psi_i, alpha, out);
}

// round 5
// speedup vs baseline: 22.1327x; 1.0378x over previous
#include <cuda_runtime.h>

#define HALF_DT 0.05f
#define A1024f 0.0061359231515f   /* 2*pi/1024 */

__device__ float2 g_mult[1024];   // M(f)/1024 at table pos p = 32j + s2, f = j + 32*sig(s2)

__device__ __forceinline__ float2 cadd(float2 a, float2 b){ return make_float2(a.x+b.x, a.y+b.y); }
__device__ __forceinline__ float2 csub(float2 a, float2 b){ return make_float2(a.x-b.x, a.y-b.y); }
__device__ __forceinline__ float2 cmul(float2 a, float2 b){
    return make_float2(fmaf(a.x, b.x, -a.y*b.y), fmaf(a.x, b.y, a.y*b.x));
}

// digit-reversal of the 4-2-4 mixed-radix length-32 FFT (involution)
__device__ __host__ __forceinline__ int sig(int s){ return ((s & 3) << 3) | (s & 4) | (s >> 3); }

// ---------- pre-kernel: spectral Cayley multiplier in pipeline order ----------
__global__ void build_mult(const float* __restrict__ hw) {
    int p = blockIdx.x * blockDim.x + threadIdx.x;   // 0..1023
    if (p >= 1024) return;
    float w[15];
    #pragma unroll
    for (int k = 0; k < 15; k++) w[k] = hw[k];
    const int offs[11] = {1,2,3,4,5,6,8,10,12,16,20};
    float wm[11];
    wm[0]=w[0]; wm[1]=w[1]+w[5]; wm[2]=w[2]; wm[3]=w[3]+w[6]+w[10]; wm[4]=w[4];
    wm[5]=w[7]; wm[6]=w[8]+w[11]; wm[7]=w[9]; wm[8]=w[12]; wm[9]=w[13]; wm[10]=w[14];
    int j  = p >> 5, s2 = p & 31;
    int f  = j + 32 * sig(s2);
    float lam = 0.0f;
    #pragma unroll
    for (int k = 0; k < 11; k++)
        lam += 2.0f * wm[k] * (1.0f - cospif((float)(offs[k] * f) * (1.0f/512.0f)));
    float sl  = HALF_DT * lam;
    float den = 1.0f + sl * sl;
    // M(f) = ((1 - sl^2) - 2 i sl)/den ; fold 1/1024
    g_mult[p] = make_float2((1.0f - sl*sl) / (den * 1024.0f),
                            (-2.0f * sl)   / (den * 1024.0f));
}

// radix-4 butterfly: DFT4 (INV=false) / IDFT4 (INV=true)
template<bool INV>
__device__ __forceinline__ void bf4(float2& A, float2& B, float2& C, float2& D){
    float2 t0 = cadd(A, C), t1 = csub(A, C);
    float2 t2 = cadd(B, D), t3 = csub(B, D);
    A = cadd(t0, t2); C = csub(t0, t2);
    if (!INV) {
        B = make_float2(t1.x + t3.y, t1.y - t3.x);   // t1 - i t3
        D = make_float2(t1.x - t3.y, t1.y + t3.x);   // t1 + i t3
    } else {
        B = make_float2(t1.x - t3.y, t1.y + t3.x);   // t1 + i t3
        D = make_float2(t1.x + t3.y, t1.y - t3.x);   // t1 - i t3
    }
}

// in-register length-32 DFT/IDFT (DIF, radix 4-2-4), natural input,
// output slot s holds index sig(s). All twiddles compile-time constants.
template<bool INV>
__device__ __forceinline__ void fft32(float2* r){
    const float C32[8] = {1.0f, 0.98078528f, 0.92387953f, 0.83146961f,
                          0.70710678f, 0.55557023f, 0.38268343f, 0.19509032f};
    const float S32[8] = {0.0f, 0.19509032f, 0.38268343f, 0.55557023f,
                          0.70710678f, 0.83146961f, 0.92387953f, 0.98078528f};
    // stage 1: radix-4, stride 8, twiddles W32^{q},W32^{2q},W32^{3q}
    #pragma unroll
    for (int q = 0; q < 8; q++){
        bf4<INV>(r[q], r[q+8], r[q+16], r[q+24]);
        if (q){
            float2 W1 = make_float2(C32[q], INV ? S32[q] : -S32[q]);
            float2 W2 = cmul(W1, W1), W3 = cmul(W2, W1);
            r[q+8]  = cmul(r[q+8],  W1);
            r[q+16] = cmul(r[q+16], W2);
            r[q+24] = cmul(r[q+24], W3);
        }
    }
    // stage 2: radix-2, stride 4, twiddles W8^q on the difference branch
    const float SQ = 0.70710678118654752f;
    #pragma unroll
    for (int b = 0; b < 4; b++){
        float2* s = r + 8*b;
        #pragma unroll
        for (int q = 0; q < 4; q++){
            float2 d = csub(s[q], s[q+4]);
            s[q] = cadd(s[q], s[q+4]);
            s[q+4] = d;
        }
        if (!INV) {
            s[5] = cmul(s[5], make_float2(SQ, -SQ));          // W8^1
            s[6] = make_float2(s[6].y, -s[6].x);              // * (-i)
            s[7] = cmul(s[7], make_float2(-SQ, -SQ));         // W8^3
        } else {
            s[5] = cmul(s[5], make_float2(SQ,  SQ));
            s[6] = make_float2(-s[6].y, s[6].x);              // * (+i)
            s[7] = cmul(s[7], make_float2(-SQ,  SQ));
        }
    }
    // stage 3: radix-4, stride 1, twiddle-free
    #pragma unroll
    for (int c = 0; c < 8; c++) bf4<INV>(r[4*c], r[4*c+1], r[4*c+2], r[4*c+3]);
}

__global__ __launch_bounds__(32, 16)
void cayley_fft_kernel(const float* __restrict__ psi_r,
                       const float* __restrict__ psi_i,
                       const float* __restrict__ alpha,
                       float2* __restrict__ out) {
    __shared__ float2 sx[1024];
    const int t = threadIdx.x;                 // 0..31
    const long long sys = blockIdx.x;
    const float* __restrict__ gr = psi_r + sys * 1024;
    const float* __restrict__ gi = psi_i + sys * 1024;

    // ---- load 32 elems (n = t + 32k, coalesced), intensity ----
    float2 r[32];
    float isum = 0.0f;
    #pragma unroll
    for (int k = 0; k < 32; k++){
        int i = t + 32*k;
        r[k] = make_float2(gr[i], gi[i]);
        isum += r[k].x * r[k].x + r[k].y * r[k].y;
    }
    #pragma unroll
    for (int o = 16; o > 0; o >>= 1) isum += __shfl_xor_sync(0xffffffffu, isum, o);
    const float inv_mean = 1.0f / (isum * (1.0f/1024.0f) + 1e-8f);

    // ---- nonlinear phase rotation ----
    #pragma unroll
    for (int k = 0; k < 32; k++){
        int i = t + 32*k;
        float inten = (r[k].x * r[k].x + r[k].y * r[k].y) * inv_mean;
        float ph = alpha[i] * inten;
        float s, c;
        __sincosf(ph, &s, &c);
        r[k] = make_float2(r[k].x * c - r[k].y * s, r[k].x * s + r[k].y * c);
    }

    // ---- phase 1: FFT32 over k; slot s holds j = sig(s) ----
    fft32<false>(r);

    // inter-phase twiddle W_1024^{t*j}: chain of powers of e^{-2pi i t/1024}
    float s0, c0;
    __sincosf((float)t * A1024f, &s0, &c0);
    {
        float2 base = make_float2(c0, -s0), w = base;
        #pragma unroll
        for (int j = 1; j < 32; j++){ r[sig(j)] = cmul(r[sig(j)], w); w = cmul(w, base); }
    }

    // ---- exchange 1: (j,t) transpose, swizzled, warp-synchronous ----
    #pragma unroll
    for (int s = 0; s < 32; s++) sx[32*sig(s) + (t ^ sig(s))] = r[s];
    __syncwarp();
    #pragma unroll
    for (int e = 0; e < 32; e++) r[e] = sx[32*t + (e ^ t)];
    __syncwarp();   // buffer reused by exchange 2

    // ---- phase 2: FFT32 over t; slot s2 holds spectrum at f = j + 32*sig(s2) ----
    fft32<false>(r);

    // ---- spectral multiply (table in pipeline order, float4 loads) ----
    {
        const float4* Mp = (const float4*)g_mult;
        #pragma unroll
        for (int c = 0; c < 16; c++){
            float4 m = Mp[16*t + c];
            r[2*c]   = cmul(r[2*c],   make_float2(m.x, m.y));
            r[2*c+1] = cmul(r[2*c+1], make_float2(m.z, m.w));
        }
    }

    // ---- reorder slots to natural h order (sig is an involution: register swaps) ----
    #pragma unroll
    for (int d = 0; d < 2; d++)
        #pragma unroll
        for (int b = 0; b < 4; b++)
            #pragma unroll
            for (int e = b + 1; e < 4; e++){
                int i1 = 8*b + 4*d + e, i2 = 8*e + 4*d + b;
                float2 tmp = r[i1]; r[i1] = r[i2]; r[i2] = tmp;
            }

    // ---- phase 3: IFFT32 over h; slot s holds u at position sig(s) ----
    fft32<true>(r);

    // inter-phase twiddle W_1024^{-t'*j}: powers of e^{+2pi i t/1024} (t == j here)
    {
        float2 base = make_float2(c0, s0), w = base;
        #pragma unroll
        for (int j = 1; j < 32; j++){ r[sig(j)] = cmul(r[sig(j)], w); w = cmul(w, base); }
    }

    // ---- exchange 2: same addressing ----
    #pragma unroll
    for (int s = 0; s < 32; s++) sx[32*sig(s) + (t ^ sig(s))] = r[s];
    __syncwarp();
    #pragma unroll
    for (int e = 0; e < 32; e++) r[e] = sx[32*t + (e ^ t)];

    // ---- phase 4: IFFT32 over j; slot s holds x[t + 32*sig(s)] ----
    fft32<true>(r);

    // ---- coalesced store ----
    float2* __restrict__ o = out + sys * 1024;
    #pragma unroll
    for (int s = 0; s < 32; s++) o[t + 32*sig(s)] = r[s];
}

extern "C" void kernel_launch(void* const* d_in, const int* in_sizes, int n_in,
                              void* d_out, int out_size) {
    const float* psi_r = (const float*)d_in[0];
    const float* psi_i = (const float*)d_in[1];
    const float* alpha = (const float*)d_in[2];
    const float* ham_w = (const float*)d_in[3];
    float2* out = (float2*)d_out;

    const int nsys = in_sizes[0] / 1024;   // B*S = 16384

    build_mult<<<4, 256>>>(ham_w);
    cayley_fft_kernel<<<nsys, 32>>>(psi_r, psi_i, alpha, out);
}